// round 4
// baseline (speedup 1.0000x reference)
#include <cuda_runtime.h>
#include <cuda_fp16.h>
#include <math.h>
#include <stdint.h>

#define S_IMG 2048
#define S_TXT 256
#define SEQ   2304
#define DIM   3072
#define HEADS 24
#define HD    128

#define QSCALE 0.12751743f   // (1/sqrt(128)) * log2(e)

// ---------------- scratch (device globals: allocation-free) ----------------
__device__ float g_q[SEQ * DIM];
__device__ float g_k[SEQ * DIM];
__device__ float g_v[SEQ * DIM];
__device__ __half g_xh[SEQ * DIM];
__device__ __half g_xl[SEQ * DIM];
__device__ __half g_qh[SEQ * DIM];
__device__ __half g_ql[SEQ * DIM];
__device__ __half g_kh[SEQ * DIM];
__device__ __half g_kl[SEQ * DIM];
__device__ __half g_vh[SEQ * DIM];
__device__ __half g_ah[S_IMG * DIM];
__device__ __half g_al[S_IMG * DIM];
__device__ __half g_wqh[DIM * DIM];
__device__ __half g_wql[DIM * DIM];
__device__ __half g_wkh[DIM * DIM];
__device__ __half g_wkl[DIM * DIM];
__device__ __half g_wvh[DIM * DIM];
__device__ __half g_wvl[DIM * DIM];
__device__ __half g_woh[DIM * DIM];
__device__ __half g_wol[DIM * DIM];

__device__ __forceinline__ float ex2(float x) {
    float r;
    asm("ex2.approx.f32 %0, %1;" : "=f"(r) : "f"(x));
    return r;
}
__device__ __forceinline__ void cpasync16(uint32_t s, const void* g) {
    asm volatile("cp.async.cg.shared.global [%0], [%1], 16;" :: "r"(s), "l"(g));
}
__device__ __forceinline__ void mma_f16(float* c, const uint32_t* a, const uint32_t* b) {
    asm volatile("mma.sync.aligned.m16n8k16.row.col.f32.f16.f16.f32 "
        "{%0,%1,%2,%3},{%4,%5,%6,%7},{%8,%9},{%0,%1,%2,%3};"
        : "+f"(c[0]), "+f"(c[1]), "+f"(c[2]), "+f"(c[3])
        : "r"(a[0]), "r"(a[1]), "r"(a[2]), "r"(a[3]), "r"(b[0]), "r"(b[1]));
}
__device__ __forceinline__ void ldsm4(uint32_t* r, uint32_t addr) {
    asm volatile("ldmatrix.sync.aligned.m8n8.x4.shared.b16 {%0,%1,%2,%3}, [%4];"
        : "=r"(r[0]), "=r"(r[1]), "=r"(r[2]), "=r"(r[3]) : "r"(addr));
}
__device__ __forceinline__ void ldsm4t(uint32_t* r, uint32_t addr) {
    asm volatile("ldmatrix.sync.aligned.m8n8.x4.trans.shared.b16 {%0,%1,%2,%3}, [%4];"
        : "=r"(r[0]), "=r"(r[1]), "=r"(r[2]), "=r"(r[3]) : "r"(addr));
}
__device__ __forceinline__ uint32_t packh2(float x, float y) {
    __half2 h = __floats2half2_rn(x, y);
    return *reinterpret_cast<uint32_t*>(&h);
}

// ---------------- fp32 -> split fp16 hi/lo ----------------
__device__ __forceinline__ void split4(float4 v, __half2* dh, __half2* dl, int i) {
    __half2 h0 = __floats2half2_rn(v.x, v.y);
    __half2 h1 = __floats2half2_rn(v.z, v.w);
    float2 f0 = __half22float2(h0), f1 = __half22float2(h1);
    dh[2 * i]     = h0;
    dh[2 * i + 1] = h1;
    dl[2 * i]     = __floats2half2_rn(v.x - f0.x, v.y - f0.y);
    dl[2 * i + 1] = __floats2half2_rn(v.z - f1.x, v.w - f1.y);
}

__global__ void concat_split_x(const float* __restrict__ hid, const float* __restrict__ enc) {
    int i = blockIdx.x * 256 + threadIdx.x;          // float4 index
    const int n_img = S_IMG * DIM / 4;
    float4 v = (i < n_img) ? reinterpret_cast<const float4*>(hid)[i]
                           : reinterpret_cast<const float4*>(enc)[i - n_img];
    split4(v, reinterpret_cast<__half2*>(g_xh), reinterpret_cast<__half2*>(g_xl), i);
}

__global__ void split_w(const float* __restrict__ src, __half* __restrict__ dh,
                        __half* __restrict__ dl) {
    int i = blockIdx.x * 256 + threadIdx.x;          // float4 index
    float4 v = reinterpret_cast<const float4*>(src)[i];
    split4(v, reinterpret_cast<__half2*>(dh), reinterpret_cast<__half2*>(dl), i);
}

// ---------------- split-fp16 tensor-core GEMM: C = A @ B + bias ----------------
// 128x128 tile, BK=32, 256 threads = 2x4 warps (warp tile 64x32), 4-stage cp.async.
// A = Ah+Al [M,K] halves, B = Bh+Bl [K,N] halves. C fp32.
#define GA_PITCH 40                      // halves per A row (32 + 8 pad)
#define GB_PITCH 136                     // halves per B row (128 + 8 pad)
#define GA_BYTES (128 * GA_PITCH * 2)    // 10240
#define GB_BYTES (32 * GB_PITCH * 2)     // 8704
#define GSTAGE   (2 * GA_BYTES + 2 * GB_BYTES)   // 37888
#define GEMM_SMEM (4 * GSTAGE)                   // 151552

__global__ __launch_bounds__(256, 1) void gemm_f16x3(
    const __half* __restrict__ Ah, const __half* __restrict__ Al,
    const __half* __restrict__ Bh, const __half* __restrict__ Bl,
    const float* __restrict__ bias, float* __restrict__ C,
    int M, int N, int K)
{
    extern __shared__ char smraw[];
    const int t    = threadIdx.x;
    const int lane = t & 31, warp = t >> 5;
    const int wm   = (warp >> 2) * 64;
    const int wn   = (warp & 3) * 32;
    const int grp  = lane >> 2, kq = lane & 3;
    const int row0 = blockIdx.y * 128, col0 = blockIdx.x * 128;
    const int KT   = K / 32;

    float c[4][4][4];
    #pragma unroll
    for (int mi = 0; mi < 4; mi++)
        #pragma unroll
        for (int ni = 0; ni < 4; ni++)
            #pragma unroll
            for (int r = 0; r < 4; r++) c[mi][ni][r] = 0.0f;

    const uint32_t sbase = (uint32_t)__cvta_generic_to_shared(smraw);

    // per-stage loader: 8 cp.async x 16B per thread
    auto load_stage = [&](int st, int k0) {
        uint32_t sa = sbase + st * GSTAGE;
        #pragma unroll
        for (int i = 0; i < 2; i++) {
            int cch = t + i * 256;                   // 0..511
            int ar = cch >> 2, ac = (cch & 3) * 8;   // A: 128 rows x 32 halves
            size_t ga = (size_t)(row0 + ar) * K + k0 + ac;
            cpasync16(sa + (ar * GA_PITCH + ac) * 2, Ah + ga);
            cpasync16(sa + GA_BYTES + (ar * GA_PITCH + ac) * 2, Al + ga);
            int br = cch >> 4, bc = (cch & 15) * 8;  // B: 32 rows x 128 halves
            size_t gb = (size_t)(k0 + br) * N + col0 + bc;
            cpasync16(sa + 2 * GA_BYTES + (br * GB_PITCH + bc) * 2, Bh + gb);
            cpasync16(sa + 2 * GA_BYTES + GB_BYTES + (br * GB_PITCH + bc) * 2, Bl + gb);
        }
    };

    #pragma unroll
    for (int s = 0; s < 3; s++) {
        load_stage(s, s * 32);
        asm volatile("cp.async.commit_group;");
    }

    // lane-invariant fragment address offsets (bytes)
    const uint32_t aoff = ((lane & 15) * GA_PITCH + (lane >> 4) * 8) * 2;
    const uint32_t boff = ((lane & 15) * GB_PITCH + (lane >> 4) * 8) * 2;

    for (int kt = 0; kt < KT; kt++) {
        asm volatile("cp.async.wait_group 2;");
        __syncthreads();

        if (kt + 3 < KT) load_stage((kt + 3) & 3, (kt + 3) * 32);
        asm volatile("cp.async.commit_group;");

        const uint32_t sa  = sbase + (kt & 3) * GSTAGE;
        const uint32_t sal = sa + GA_BYTES;
        const uint32_t sbh = sa + 2 * GA_BYTES;
        const uint32_t sbl = sbh + GB_BYTES;

        #pragma unroll
        for (int ks = 0; ks < 2; ks++) {
            uint32_t ah[4][4], al4[4][4], bh[4][2], bl4[4][2];
            #pragma unroll
            for (int mi = 0; mi < 4; mi++) {
                uint32_t off = aoff + ((wm + mi * 16) * GA_PITCH + ks * 16) * 2;
                ldsm4(ah[mi],  sa  + off);
                ldsm4(al4[mi], sal + off);
            }
            #pragma unroll
            for (int np = 0; np < 2; np++) {
                uint32_t off = boff + (ks * 16 * GB_PITCH + wn + np * 16) * 2;
                uint32_t rh[4], rl[4];
                ldsm4t(rh, sbh + off);
                ldsm4t(rl, sbl + off);
                bh[2 * np][0] = rh[0]; bh[2 * np][1] = rh[1];
                bh[2 * np + 1][0] = rh[2]; bh[2 * np + 1][1] = rh[3];
                bl4[2 * np][0] = rl[0]; bl4[2 * np][1] = rl[1];
                bl4[2 * np + 1][0] = rl[2]; bl4[2 * np + 1][1] = rl[3];
            }
            #pragma unroll
            for (int mi = 0; mi < 4; mi++)
                #pragma unroll
                for (int ni = 0; ni < 4; ni++) {
                    mma_f16(c[mi][ni], ah[mi],  bh[ni]);
                    mma_f16(c[mi][ni], ah[mi],  bl4[ni]);
                    mma_f16(c[mi][ni], al4[mi], bh[ni]);
                }
        }
        __syncthreads();
    }

    #pragma unroll
    for (int mi = 0; mi < 4; mi++) {
        int r = row0 + wm + mi * 16 + grp;
        #pragma unroll
        for (int ni = 0; ni < 4; ni++) {
            int cc = col0 + wn + ni * 8 + 2 * kq;
            float2 bsv = *reinterpret_cast<const float2*>(&bias[cc]);
            float2 o0 = make_float2(c[mi][ni][0] + bsv.x, c[mi][ni][1] + bsv.y);
            float2 o1 = make_float2(c[mi][ni][2] + bsv.x, c[mi][ni][3] + bsv.y);
            *reinterpret_cast<float2*>(&C[(size_t)r * N + cc]) = o0;
            *reinterpret_cast<float2*>(&C[(size_t)(r + 8) * N + cc]) = o1;
        }
    }
}

// ---------------- per-head RMSNorm + RoPE -> split fp16 hi/lo ----------------
__global__ __launch_bounds__(128) void norm_rope_split(
    const float* __restrict__ buf, const float* __restrict__ w,
    const float* __restrict__ rc, const float* __restrict__ rs,
    __half* __restrict__ oh, __half* __restrict__ ol, float fold)
{
    const int s = blockIdx.x, h = blockIdx.y, t = threadIdx.x;
    const float* p = buf + (size_t)s * DIM + h * HD;
    float x = p[t];
    float ss = x * x;
    #pragma unroll
    for (int off = 16; off; off >>= 1) ss += __shfl_xor_sync(0xffffffffu, ss, off);
    __shared__ float wsum[4];
    if ((t & 31) == 0) wsum[t >> 5] = ss;
    __syncthreads();
    float tot = wsum[0] + wsum[1] + wsum[2] + wsum[3];
    float r = rsqrtf(tot * (1.0f / HD) + 1e-6f);
    float val = x * r * w[t];
    if (s < S_IMG) {
        float prt = __shfl_xor_sync(0xffffffffu, val, 1);
        float rot = (t & 1) ? prt : -prt;
        val = val * rc[s * HD + t] + rot * rs[s * HD + t];
    }
    float y = val * fold;
    __half hi = __float2half_rn(y);
    __half lo = __float2half_rn(y - __half2float(hi));
    size_t idx = (size_t)s * DIM + h * HD + t;
    oh[idx] = hi;
    ol[idx] = lo;
}

// ---------------- V fp32 -> fp16 ----------------
__global__ void convert_vh() {
    int i = blockIdx.x * 256 + threadIdx.x;     // float4 index
    float4 v = reinterpret_cast<const float4*>(g_v)[i];
    reinterpret_cast<__half2*>(g_vh)[2 * i]     = __floats2half2_rn(v.x, v.y);
    reinterpret_cast<__half2*>(g_vh)[2 * i + 1] = __floats2half2_rn(v.z, v.w);
}

// ---------------- tensor-core flash attention ----------------
#define AT_QH 0
#define AT_QL 17408
#define AT_KH 34816
#define AT_KL 43520
#define AT_VT 52224
#define ATTN_SMEM ((52224 + 9216) * 2)   // 122880 bytes

__global__ __launch_bounds__(256, 1) void attn_tc(float* __restrict__ out) {
    extern __shared__ __half sh[];
    __half* Vt = sh + AT_VT;

    const int t = threadIdx.x, lane = t & 31, w = t >> 5;
    const int grp = lane >> 2, kq = lane & 3;
    const int h = blockIdx.y, q0 = blockIdx.x * 128, m0 = w * 16;

    uint32_t sb  = (uint32_t)__cvta_generic_to_shared(sh);
    uint32_t sqh = sb + AT_QH * 2, sql = sb + AT_QL * 2;
    uint32_t skh = sb + AT_KH * 2, skl = sb + AT_KL * 2;

    __half* Qh = sh + AT_QH;
    __half* Ql = sh + AT_QL;
    __half* Kh = sh + AT_KH;
    __half* Kl = sh + AT_KL;

    #pragma unroll
    for (int i = 0; i < 8; i++) {
        int c = t + i * 256, r = c >> 4, off = (c & 15) * 16;
        const char* bh = (const char*)(g_qh + (size_t)(q0 + r) * DIM + h * HD) + off;
        const char* bl = (const char*)(g_ql + (size_t)(q0 + r) * DIM + h * HD) + off;
        cpasync16(sqh + r * 272 + off, bh);
        cpasync16(sql + r * 272 + off, bl);
    }
    asm volatile("cp.async.commit_group;");

    float O[16][4];
    #pragma unroll
    for (int nt = 0; nt < 16; nt++)
        #pragma unroll
        for (int r = 0; r < 4; r++) O[nt][r] = 0.0f;
    float mrow0 = -INFINITY, mrow1 = -INFINITY, lrow0 = 0.0f, lrow1 = 0.0f;

    for (int kt = 0; kt < 36; kt++) {
        const int k0 = kt * 64;
        #pragma unroll
        for (int i = 0; i < 4; i++) {
            int c = t + i * 256, r = c >> 4, off = (c & 15) * 16;
            const char* bh = (const char*)(g_kh + (size_t)(k0 + r) * DIM + h * HD) + off;
            const char* bl = (const char*)(g_kl + (size_t)(k0 + r) * DIM + h * HD) + off;
            cpasync16(skh + r * 272 + off, bh);
            cpasync16(skl + r * 272 + off, bl);
        }
        asm volatile("cp.async.commit_group;");

        {
            int sr = t >> 3, dc = (t & 7) * 16;
            #pragma unroll
            for (int pass = 0; pass < 2; pass++) {
                int s = pass * 32 + sr;
                const __half2* src = reinterpret_cast<const __half2*>(
                    g_vh + (size_t)(k0 + s) * DIM + h * HD + dc);
                #pragma unroll
                for (int j = 0; j < 8; j++) {
                    __half2 v2 = src[j];
                    Vt[(dc + 2 * j) * 72 + s]     = __low2half(v2);
                    Vt[(dc + 2 * j + 1) * 72 + s] = __high2half(v2);
                }
            }
        }
        asm volatile("cp.async.wait_group 0;");
        __syncthreads();

        float S[8][4];
        #pragma unroll
        for (int n = 0; n < 8; n++)
            #pragma unroll
            for (int r = 0; r < 4; r++) S[n][r] = 0.0f;

        #pragma unroll
        for (int ks = 0; ks < 8; ks++) {
            uint32_t ah[4], al[4];
            const __half* qb  = Qh + (m0 + grp) * 136 + ks * 16 + 2 * kq;
            const __half* ql2 = Ql + (m0 + grp) * 136 + ks * 16 + 2 * kq;
            ah[0] = *(const uint32_t*)qb;
            ah[1] = *(const uint32_t*)(qb + 8 * 136);
            ah[2] = *(const uint32_t*)(qb + 8);
            ah[3] = *(const uint32_t*)(qb + 8 * 136 + 8);
            al[0] = *(const uint32_t*)ql2;
            al[1] = *(const uint32_t*)(ql2 + 8 * 136);
            al[2] = *(const uint32_t*)(ql2 + 8);
            al[3] = *(const uint32_t*)(ql2 + 8 * 136 + 8);
            #pragma unroll
            for (int n = 0; n < 8; n++) {
                const __half* kb  = Kh + (n * 8 + grp) * 136 + ks * 16 + 2 * kq;
                const __half* kb2 = Kl + (n * 8 + grp) * 136 + ks * 16 + 2 * kq;
                uint32_t bh[2], bl2[2];
                bh[0]  = *(const uint32_t*)kb;  bh[1]  = *(const uint32_t*)(kb + 8);
                bl2[0] = *(const uint32_t*)kb2; bl2[1] = *(const uint32_t*)(kb2 + 8);
                mma_f16(S[n], ah, bh);
                mma_f16(S[n], ah, bl2);
                mma_f16(S[n], al, bh);
            }
        }

        float mx0 = -INFINITY, mx1 = -INFINITY;
        #pragma unroll
        for (int n = 0; n < 8; n++) {
            mx0 = fmaxf(mx0, fmaxf(S[n][0], S[n][1]));
            mx1 = fmaxf(mx1, fmaxf(S[n][2], S[n][3]));
        }
        mx0 = fmaxf(mx0, __shfl_xor_sync(0xffffffffu, mx0, 1));
        mx0 = fmaxf(mx0, __shfl_xor_sync(0xffffffffu, mx0, 2));
        mx1 = fmaxf(mx1, __shfl_xor_sync(0xffffffffu, mx1, 1));
        mx1 = fmaxf(mx1, __shfl_xor_sync(0xffffffffu, mx1, 2));

        float mn0 = fmaxf(mrow0, mx0), mn1 = fmaxf(mrow1, mx1);
        float a0 = ex2(mrow0 - mn0), a1 = ex2(mrow1 - mn1);
        float rs0 = 0.0f, rs1 = 0.0f;
        #pragma unroll
        for (int n = 0; n < 8; n++) {
            S[n][0] = ex2(S[n][0] - mn0);
            S[n][1] = ex2(S[n][1] - mn0);
            S[n][2] = ex2(S[n][2] - mn1);
            S[n][3] = ex2(S[n][3] - mn1);
            rs0 += S[n][0] + S[n][1];
            rs1 += S[n][2] + S[n][3];
        }
        rs0 += __shfl_xor_sync(0xffffffffu, rs0, 1);
        rs0 += __shfl_xor_sync(0xffffffffu, rs0, 2);
        rs1 += __shfl_xor_sync(0xffffffffu, rs1, 1);
        rs1 += __shfl_xor_sync(0xffffffffu, rs1, 2);
        lrow0 = lrow0 * a0 + rs0;
        lrow1 = lrow1 * a1 + rs1;
        mrow0 = mn0; mrow1 = mn1;

        #pragma unroll
        for (int nt = 0; nt < 16; nt++) {
            O[nt][0] *= a0; O[nt][1] *= a0;
            O[nt][2] *= a1; O[nt][3] *= a1;
        }

        uint32_t pa[4][4];
        #pragma unroll
        for (int ks2 = 0; ks2 < 4; ks2++) {
            pa[ks2][0] = packh2(S[2 * ks2][0],     S[2 * ks2][1]);
            pa[ks2][1] = packh2(S[2 * ks2][2],     S[2 * ks2][3]);
            pa[ks2][2] = packh2(S[2 * ks2 + 1][0], S[2 * ks2 + 1][1]);
            pa[ks2][3] = packh2(S[2 * ks2 + 1][2], S[2 * ks2 + 1][3]);
        }

        #pragma unroll
        for (int ks2 = 0; ks2 < 4; ks2++) {
            #pragma unroll
            for (int nt = 0; nt < 16; nt++) {
                const __half* vb = Vt + (nt * 8 + grp) * 72 + ks2 * 16 + 2 * kq;
                uint32_t b[2];
                b[0] = *(const uint32_t*)vb;
                b[1] = *(const uint32_t*)(vb + 8);
                mma_f16(O[nt], pa[ks2], b);
            }
        }
        __syncthreads();
    }

    // --- epilogue: img rows -> split halves for Wo GEMM, txt rows -> d_out ---
    const float inv0 = 1.0f / lrow0, inv1 = 1.0f / lrow1;
    const int r = q0 + m0 + grp;
    if (blockIdx.x < 16) {
        #pragma unroll
        for (int nt = 0; nt < 16; nt++) {
            float o0 = O[nt][0] * inv0, o1 = O[nt][1] * inv0;
            float o2 = O[nt][2] * inv1, o3 = O[nt][3] * inv1;
            int cc = h * HD + nt * 8 + 2 * kq;
            __half2 h0 = __floats2half2_rn(o0, o1);
            __half2 h1 = __floats2half2_rn(o2, o3);
            float2 f0 = __half22float2(h0), f1 = __half22float2(h1);
            *reinterpret_cast<__half2*>(&g_ah[(size_t)r * DIM + cc]) = h0;
            *reinterpret_cast<__half2*>(&g_ah[(size_t)(r + 8) * DIM + cc]) = h1;
            *reinterpret_cast<__half2*>(&g_al[(size_t)r * DIM + cc]) =
                __floats2half2_rn(o0 - f0.x, o1 - f0.y);
            *reinterpret_cast<__half2*>(&g_al[(size_t)(r + 8) * DIM + cc]) =
                __floats2half2_rn(o2 - f1.x, o3 - f1.y);
        }
    } else {
        #pragma unroll
        for (int nt = 0; nt < 16; nt++) {
            int cc = h * HD + nt * 8 + 2 * kq;
            *reinterpret_cast<float2*>(&out[(size_t)r * DIM + cc]) =
                make_float2(O[nt][0] * inv0, O[nt][1] * inv0);
            *reinterpret_cast<float2*>(&out[(size_t)(r + 8) * DIM + cc]) =
                make_float2(O[nt][2] * inv1, O[nt][3] * inv1);
        }
    }
}

// ---------------- launch ----------------
extern "C" void kernel_launch(void* const* d_in, const int* in_sizes, int n_in,
                              void* d_out, int out_size) {
    const float* hid  = (const float*)d_in[0];
    const float* enc  = (const float*)d_in[1];
    const float* rcos = (const float*)d_in[2];
    const float* rsin = (const float*)d_in[3];
    const float* Wq   = (const float*)d_in[4];
    const float* bq   = (const float*)d_in[5];
    const float* Wk   = (const float*)d_in[6];
    const float* bk   = (const float*)d_in[7];
    const float* Wv   = (const float*)d_in[8];
    const float* bv   = (const float*)d_in[9];
    const float* nqw  = (const float*)d_in[10];
    const float* nkw  = (const float*)d_in[11];
    const float* Wo   = (const float*)d_in[12];
    const float* bo   = (const float*)d_in[13];
    float* out = (float*)d_out;

    float *pq, *pk, *pv;
    cudaGetSymbolAddress((void**)&pq, g_q);
    cudaGetSymbolAddress((void**)&pk, g_k);
    cudaGetSymbolAddress((void**)&pv, g_v);
    __half *pxh, *pxl, *pqh, *pql, *pkh, *pkl, *pah, *pal;
    __half *pwqh, *pwql, *pwkh, *pwkl, *pwvh, *pwvl, *pwoh, *pwol;
    cudaGetSymbolAddress((void**)&pxh, g_xh);
    cudaGetSymbolAddress((void**)&pxl, g_xl);
    cudaGetSymbolAddress((void**)&pqh, g_qh);
    cudaGetSymbolAddress((void**)&pql, g_ql);
    cudaGetSymbolAddress((void**)&pkh, g_kh);
    cudaGetSymbolAddress((void**)&pkl, g_kl);
    cudaGetSymbolAddress((void**)&pah, g_ah);
    cudaGetSymbolAddress((void**)&pal, g_al);
    cudaGetSymbolAddress((void**)&pwqh, g_wqh);
    cudaGetSymbolAddress((void**)&pwql, g_wql);
    cudaGetSymbolAddress((void**)&pwkh, g_wkh);
    cudaGetSymbolAddress((void**)&pwkl, g_wkl);
    cudaGetSymbolAddress((void**)&pwvh, g_wvh);
    cudaGetSymbolAddress((void**)&pwvl, g_wvl);
    cudaGetSymbolAddress((void**)&pwoh, g_woh);
    cudaGetSymbolAddress((void**)&pwol, g_wol);

    cudaFuncSetAttribute(gemm_f16x3, cudaFuncAttributeMaxDynamicSharedMemorySize, GEMM_SMEM);
    cudaFuncSetAttribute(attn_tc, cudaFuncAttributeMaxDynamicSharedMemorySize, ATTN_SMEM);

    concat_split_x<<<SEQ * DIM / 1024, 256>>>(hid, enc);

    const int nw4 = DIM * DIM / 1024;
    split_w<<<nw4, 256>>>(Wq, pwqh, pwql);
    split_w<<<nw4, 256>>>(Wk, pwkh, pwkl);
    split_w<<<nw4, 256>>>(Wv, pwvh, pwvl);
    split_w<<<nw4, 256>>>(Wo, pwoh, pwol);

    dim3 gqkv(DIM / 128, SEQ / 128);
    gemm_f16x3<<<gqkv, 256, GEMM_SMEM>>>(pxh, pxl, pwqh, pwql, bq, pq, SEQ, DIM, DIM);
    gemm_f16x3<<<gqkv, 256, GEMM_SMEM>>>(pxh, pxl, pwkh, pwkl, bk, pk, SEQ, DIM, DIM);
    gemm_f16x3<<<gqkv, 256, GEMM_SMEM>>>(pxh, pxl, pwvh, pwvl, bv, pv, SEQ, DIM, DIM);

    dim3 gn(SEQ, HEADS);
    norm_rope_split<<<gn, 128>>>(pq, nqw, rcos, rsin, pqh, pql, QSCALE);
    norm_rope_split<<<gn, 128>>>(pk, nkw, rcos, rsin, pkh, pkl, 1.0f);
    convert_vh<<<SEQ * DIM / 1024, 256>>>();

    dim3 ga(SEQ / 128, HEADS);
    attn_tc<<<ga, 256, ATTN_SMEM>>>(out);

    dim3 gout(DIM / 128, S_IMG / 128);
    gemm_f16x3<<<gout, 256, GEMM_SMEM>>>(pah, pal, pwoh, pwol, bo, out, S_IMG, DIM, DIM);
}

// round 5
// speedup vs baseline: 1.6482x; 1.6482x over previous
#include <cuda_runtime.h>
#include <cuda_fp16.h>
#include <math.h>
#include <stdint.h>

#define S_IMG 2048
#define S_TXT 256
#define SEQ   2304
#define DIM   3072
#define HEADS 24
#define HD    128

#define QSCALE 0.12751743f   // (1/sqrt(128)) * log2(e)

// ---------------- scratch (device globals: allocation-free) ----------------
__device__ float g_q[SEQ * DIM];
__device__ float g_k[SEQ * DIM];
__device__ float g_v[SEQ * DIM];
__device__ __half g_xh[SEQ * DIM];
__device__ __half g_qh[SEQ * DIM];
__device__ __half g_ql[SEQ * DIM];
__device__ __half g_kh[SEQ * DIM];
__device__ __half g_kl[SEQ * DIM];
__device__ __half g_vh[SEQ * DIM];
__device__ __half g_ah[S_IMG * DIM];
__device__ __half g_wqh[DIM * DIM];
__device__ __half g_wkh[DIM * DIM];
__device__ __half g_wvh[DIM * DIM];
__device__ __half g_woh[DIM * DIM];

__device__ __forceinline__ float ex2(float x) {
    float r;
    asm("ex2.approx.f32 %0, %1;" : "=f"(r) : "f"(x));
    return r;
}
__device__ __forceinline__ void cpasync16(uint32_t s, const void* g) {
    asm volatile("cp.async.cg.shared.global [%0], [%1], 16;" :: "r"(s), "l"(g));
}
__device__ __forceinline__ void mma_f16(float* c, const uint32_t* a, const uint32_t* b) {
    asm volatile("mma.sync.aligned.m16n8k16.row.col.f32.f16.f16.f32 "
        "{%0,%1,%2,%3},{%4,%5,%6,%7},{%8,%9},{%0,%1,%2,%3};"
        : "+f"(c[0]), "+f"(c[1]), "+f"(c[2]), "+f"(c[3])
        : "r"(a[0]), "r"(a[1]), "r"(a[2]), "r"(a[3]), "r"(b[0]), "r"(b[1]));
}
__device__ __forceinline__ void ldsm4(uint32_t* r, uint32_t addr) {
    asm volatile("ldmatrix.sync.aligned.m8n8.x4.shared.b16 {%0,%1,%2,%3}, [%4];"
        : "=r"(r[0]), "=r"(r[1]), "=r"(r[2]), "=r"(r[3]) : "r"(addr));
}
__device__ __forceinline__ void ldsm4t(uint32_t* r, uint32_t addr) {
    asm volatile("ldmatrix.sync.aligned.m8n8.x4.trans.shared.b16 {%0,%1,%2,%3}, [%4];"
        : "=r"(r[0]), "=r"(r[1]), "=r"(r[2]), "=r"(r[3]) : "r"(addr));
}
__device__ __forceinline__ uint32_t packh2(float x, float y) {
    __half2 h = __floats2half2_rn(x, y);
    return *reinterpret_cast<uint32_t*>(&h);
}

// ---------------- concat hidden || encoder -> fp16 ----------------
__global__ void concat_xh(const float* __restrict__ hid, const float* __restrict__ enc) {
    int i = blockIdx.x * 256 + threadIdx.x;          // float4 index
    const int n_img = S_IMG * DIM / 4;
    float4 v = (i < n_img) ? reinterpret_cast<const float4*>(hid)[i]
                           : reinterpret_cast<const float4*>(enc)[i - n_img];
    reinterpret_cast<__half2*>(g_xh)[2 * i]     = __floats2half2_rn(v.x, v.y);
    reinterpret_cast<__half2*>(g_xh)[2 * i + 1] = __floats2half2_rn(v.z, v.w);
}

// ---------------- W fp32 -> fp16 ----------------
__global__ void conv_wh(const float* __restrict__ src, __half* __restrict__ dst) {
    int i = blockIdx.x * 256 + threadIdx.x;          // float4 index
    float4 v = reinterpret_cast<const float4*>(src)[i];
    reinterpret_cast<__half2*>(dst)[2 * i]     = __floats2half2_rn(v.x, v.y);
    reinterpret_cast<__half2*>(dst)[2 * i + 1] = __floats2half2_rn(v.z, v.w);
}

// ---------------- fp16 tensor-core GEMM: C = A @ B + bias ----------------
// 128x128 tile, BK=32, 256 threads = 2x4 warps (warp tile 64x32), 4-stage cp.async.
#define GA_PITCH 40                      // halves per A row (32 + 8 pad)
#define GB_PITCH 136                     // halves per B row (128 + 8 pad)
#define GA_BYTES (128 * GA_PITCH * 2)    // 10240
#define GB_BYTES (32 * GB_PITCH * 2)     // 8704
#define GSTAGE   (GA_BYTES + GB_BYTES)   // 18944
#define GEMM_SMEM (4 * GSTAGE)           // 75776

__global__ __launch_bounds__(256, 1) void gemm_f16(
    const __half* __restrict__ A, const __half* __restrict__ B,
    const float* __restrict__ bias, float* __restrict__ C,
    int M, int N, int K)
{
    extern __shared__ char smraw[];
    const int t    = threadIdx.x;
    const int lane = t & 31, warp = t >> 5;
    const int wm   = (warp >> 2) * 64;
    const int wn   = (warp & 3) * 32;
    const int grp  = lane >> 2, kq = lane & 3;
    const int row0 = blockIdx.y * 128, col0 = blockIdx.x * 128;
    const int KT   = K / 32;

    float c[4][4][4];
    #pragma unroll
    for (int mi = 0; mi < 4; mi++)
        #pragma unroll
        for (int ni = 0; ni < 4; ni++)
            #pragma unroll
            for (int r = 0; r < 4; r++) c[mi][ni][r] = 0.0f;

    const uint32_t sbase = (uint32_t)__cvta_generic_to_shared(smraw);

    auto load_stage = [&](int st, int k0) {
        uint32_t sa = sbase + st * GSTAGE;
        #pragma unroll
        for (int i = 0; i < 2; i++) {
            int cch = t + i * 256;                   // 0..511
            int ar = cch >> 2, ac = (cch & 3) * 8;   // A: 128 rows x 32 halves
            cpasync16(sa + (ar * GA_PITCH + ac) * 2, A + (size_t)(row0 + ar) * K + k0 + ac);
            int br = cch >> 4, bc = (cch & 15) * 8;  // B: 32 rows x 128 halves
            cpasync16(sa + GA_BYTES + (br * GB_PITCH + bc) * 2,
                      B + (size_t)(k0 + br) * N + col0 + bc);
        }
    };

    #pragma unroll
    for (int s = 0; s < 3; s++) {
        load_stage(s, s * 32);
        asm volatile("cp.async.commit_group;");
    }

    const uint32_t aoff = ((lane & 15) * GA_PITCH + (lane >> 4) * 8) * 2;
    const uint32_t boff = ((lane & 15) * GB_PITCH + (lane >> 4) * 8) * 2;

    for (int kt = 0; kt < KT; kt++) {
        asm volatile("cp.async.wait_group 2;");
        __syncthreads();

        if (kt + 3 < KT) load_stage((kt + 3) & 3, (kt + 3) * 32);
        asm volatile("cp.async.commit_group;");

        const uint32_t sa = sbase + (kt & 3) * GSTAGE;
        const uint32_t sb = sa + GA_BYTES;

        #pragma unroll
        for (int ks = 0; ks < 2; ks++) {
            uint32_t ah[4][4], bh[4][2];
            #pragma unroll
            for (int mi = 0; mi < 4; mi++)
                ldsm4(ah[mi], sa + aoff + ((wm + mi * 16) * GA_PITCH + ks * 16) * 2);
            #pragma unroll
            for (int np = 0; np < 2; np++) {
                uint32_t rh[4];
                ldsm4t(rh, sb + boff + (ks * 16 * GB_PITCH + wn + np * 16) * 2);
                bh[2 * np][0] = rh[0]; bh[2 * np][1] = rh[1];
                bh[2 * np + 1][0] = rh[2]; bh[2 * np + 1][1] = rh[3];
            }
            #pragma unroll
            for (int mi = 0; mi < 4; mi++)
                #pragma unroll
                for (int ni = 0; ni < 4; ni++)
                    mma_f16(c[mi][ni], ah[mi], bh[ni]);
        }
        __syncthreads();
    }

    #pragma unroll
    for (int mi = 0; mi < 4; mi++) {
        int r = row0 + wm + mi * 16 + grp;
        #pragma unroll
        for (int ni = 0; ni < 4; ni++) {
            int cc = col0 + wn + ni * 8 + 2 * kq;
            float2 bsv = *reinterpret_cast<const float2*>(&bias[cc]);
            float2 o0 = make_float2(c[mi][ni][0] + bsv.x, c[mi][ni][1] + bsv.y);
            float2 o1 = make_float2(c[mi][ni][2] + bsv.x, c[mi][ni][3] + bsv.y);
            *reinterpret_cast<float2*>(&C[(size_t)r * N + cc]) = o0;
            *reinterpret_cast<float2*>(&C[(size_t)(r + 8) * N + cc]) = o1;
        }
    }
}

// ---------------- per-head RMSNorm + RoPE -> split fp16 hi/lo ----------------
__global__ __launch_bounds__(128) void norm_rope_split(
    const float* __restrict__ buf, const float* __restrict__ w,
    const float* __restrict__ rc, const float* __restrict__ rs,
    __half* __restrict__ oh, __half* __restrict__ ol, float fold)
{
    const int s = blockIdx.x, h = blockIdx.y, t = threadIdx.x;
    const float* p = buf + (size_t)s * DIM + h * HD;
    float x = p[t];
    float ss = x * x;
    #pragma unroll
    for (int off = 16; off; off >>= 1) ss += __shfl_xor_sync(0xffffffffu, ss, off);
    __shared__ float wsum[4];
    if ((t & 31) == 0) wsum[t >> 5] = ss;
    __syncthreads();
    float tot = wsum[0] + wsum[1] + wsum[2] + wsum[3];
    float r = rsqrtf(tot * (1.0f / HD) + 1e-6f);
    float val = x * r * w[t];
    if (s < S_IMG) {
        float prt = __shfl_xor_sync(0xffffffffu, val, 1);
        float rot = (t & 1) ? prt : -prt;
        val = val * rc[s * HD + t] + rot * rs[s * HD + t];
    }
    float y = val * fold;
    __half hi = __float2half_rn(y);
    __half lo = __float2half_rn(y - __half2float(hi));
    size_t idx = (size_t)s * DIM + h * HD + t;
    oh[idx] = hi;
    ol[idx] = lo;
}

// ---------------- V fp32 -> fp16 ----------------
__global__ void convert_vh() {
    int i = blockIdx.x * 256 + threadIdx.x;     // float4 index
    float4 v = reinterpret_cast<const float4*>(g_v)[i];
    reinterpret_cast<__half2*>(g_vh)[2 * i]     = __floats2half2_rn(v.x, v.y);
    reinterpret_cast<__half2*>(g_vh)[2 * i + 1] = __floats2half2_rn(v.z, v.w);
}

// ---------------- tensor-core flash attention ----------------
#define AT_QH 0
#define AT_QL 17408
#define AT_KH 34816
#define AT_KL 43520
#define AT_VT 52224
#define ATTN_SMEM ((52224 + 9216) * 2)   // 122880 bytes

__global__ __launch_bounds__(256, 1) void attn_tc(float* __restrict__ out) {
    extern __shared__ __half sh[];
    __half* Vt = sh + AT_VT;

    const int t = threadIdx.x, lane = t & 31, w = t >> 5;
    const int grp = lane >> 2, kq = lane & 3;
    const int h = blockIdx.y, q0 = blockIdx.x * 128, m0 = w * 16;

    uint32_t sb  = (uint32_t)__cvta_generic_to_shared(sh);
    uint32_t sqh = sb + AT_QH * 2, sql = sb + AT_QL * 2;
    uint32_t skh = sb + AT_KH * 2, skl = sb + AT_KL * 2;

    __half* Qh = sh + AT_QH;
    __half* Ql = sh + AT_QL;
    __half* Kh = sh + AT_KH;
    __half* Kl = sh + AT_KL;

    #pragma unroll
    for (int i = 0; i < 8; i++) {
        int c = t + i * 256, r = c >> 4, off = (c & 15) * 16;
        const char* bh = (const char*)(g_qh + (size_t)(q0 + r) * DIM + h * HD) + off;
        const char* bl = (const char*)(g_ql + (size_t)(q0 + r) * DIM + h * HD) + off;
        cpasync16(sqh + r * 272 + off, bh);
        cpasync16(sql + r * 272 + off, bl);
    }
    asm volatile("cp.async.commit_group;");

    float O[16][4];
    #pragma unroll
    for (int nt = 0; nt < 16; nt++)
        #pragma unroll
        for (int r = 0; r < 4; r++) O[nt][r] = 0.0f;
    float mrow0 = -INFINITY, mrow1 = -INFINITY, lrow0 = 0.0f, lrow1 = 0.0f;

    for (int kt = 0; kt < 36; kt++) {
        const int k0 = kt * 64;
        #pragma unroll
        for (int i = 0; i < 4; i++) {
            int c = t + i * 256, r = c >> 4, off = (c & 15) * 16;
            const char* bh = (const char*)(g_kh + (size_t)(k0 + r) * DIM + h * HD) + off;
            const char* bl = (const char*)(g_kl + (size_t)(k0 + r) * DIM + h * HD) + off;
            cpasync16(skh + r * 272 + off, bh);
            cpasync16(skl + r * 272 + off, bl);
        }
        asm volatile("cp.async.commit_group;");

        {
            int sr = t >> 3, dc = (t & 7) * 16;
            #pragma unroll
            for (int pass = 0; pass < 2; pass++) {
                int s = pass * 32 + sr;
                const __half2* src = reinterpret_cast<const __half2*>(
                    g_vh + (size_t)(k0 + s) * DIM + h * HD + dc);
                #pragma unroll
                for (int j = 0; j < 8; j++) {
                    __half2 v2 = src[j];
                    Vt[(dc + 2 * j) * 72 + s]     = __low2half(v2);
                    Vt[(dc + 2 * j + 1) * 72 + s] = __high2half(v2);
                }
            }
        }
        asm volatile("cp.async.wait_group 0;");
        __syncthreads();

        float S[8][4];
        #pragma unroll
        for (int n = 0; n < 8; n++)
            #pragma unroll
            for (int r = 0; r < 4; r++) S[n][r] = 0.0f;

        #pragma unroll
        for (int ks = 0; ks < 8; ks++) {
            uint32_t ah[4], al[4];
            const __half* qb  = Qh + (m0 + grp) * 136 + ks * 16 + 2 * kq;
            const __half* ql2 = Ql + (m0 + grp) * 136 + ks * 16 + 2 * kq;
            ah[0] = *(const uint32_t*)qb;
            ah[1] = *(const uint32_t*)(qb + 8 * 136);
            ah[2] = *(const uint32_t*)(qb + 8);
            ah[3] = *(const uint32_t*)(qb + 8 * 136 + 8);
            al[0] = *(const uint32_t*)ql2;
            al[1] = *(const uint32_t*)(ql2 + 8 * 136);
            al[2] = *(const uint32_t*)(ql2 + 8);
            al[3] = *(const uint32_t*)(ql2 + 8 * 136 + 8);
            #pragma unroll
            for (int n = 0; n < 8; n++) {
                const __half* kb  = Kh + (n * 8 + grp) * 136 + ks * 16 + 2 * kq;
                const __half* kb2 = Kl + (n * 8 + grp) * 136 + ks * 16 + 2 * kq;
                uint32_t bh[2], bl2[2];
                bh[0]  = *(const uint32_t*)kb;  bh[1]  = *(const uint32_t*)(kb + 8);
                bl2[0] = *(const uint32_t*)kb2; bl2[1] = *(const uint32_t*)(kb2 + 8);
                mma_f16(S[n], ah, bh);
                mma_f16(S[n], ah, bl2);
                mma_f16(S[n], al, bh);
            }
        }

        float mx0 = -INFINITY, mx1 = -INFINITY;
        #pragma unroll
        for (int n = 0; n < 8; n++) {
            mx0 = fmaxf(mx0, fmaxf(S[n][0], S[n][1]));
            mx1 = fmaxf(mx1, fmaxf(S[n][2], S[n][3]));
        }
        mx0 = fmaxf(mx0, __shfl_xor_sync(0xffffffffu, mx0, 1));
        mx0 = fmaxf(mx0, __shfl_xor_sync(0xffffffffu, mx0, 2));
        mx1 = fmaxf(mx1, __shfl_xor_sync(0xffffffffu, mx1, 1));
        mx1 = fmaxf(mx1, __shfl_xor_sync(0xffffffffu, mx1, 2));

        float mn0 = fmaxf(mrow0, mx0), mn1 = fmaxf(mrow1, mx1);
        float a0 = ex2(mrow0 - mn0), a1 = ex2(mrow1 - mn1);
        float rs0 = 0.0f, rs1 = 0.0f;
        #pragma unroll
        for (int n = 0; n < 8; n++) {
            S[n][0] = ex2(S[n][0] - mn0);
            S[n][1] = ex2(S[n][1] - mn0);
            S[n][2] = ex2(S[n][2] - mn1);
            S[n][3] = ex2(S[n][3] - mn1);
            rs0 += S[n][0] + S[n][1];
            rs1 += S[n][2] + S[n][3];
        }
        rs0 += __shfl_xor_sync(0xffffffffu, rs0, 1);
        rs0 += __shfl_xor_sync(0xffffffffu, rs0, 2);
        rs1 += __shfl_xor_sync(0xffffffffu, rs1, 1);
        rs1 += __shfl_xor_sync(0xffffffffu, rs1, 2);
        lrow0 = lrow0 * a0 + rs0;
        lrow1 = lrow1 * a1 + rs1;
        mrow0 = mn0; mrow1 = mn1;

        #pragma unroll
        for (int nt = 0; nt < 16; nt++) {
            O[nt][0] *= a0; O[nt][1] *= a0;
            O[nt][2] *= a1; O[nt][3] *= a1;
        }

        uint32_t pa[4][4];
        #pragma unroll
        for (int ks2 = 0; ks2 < 4; ks2++) {
            pa[ks2][0] = packh2(S[2 * ks2][0],     S[2 * ks2][1]);
            pa[ks2][1] = packh2(S[2 * ks2][2],     S[2 * ks2][3]);
            pa[ks2][2] = packh2(S[2 * ks2 + 1][0], S[2 * ks2 + 1][1]);
            pa[ks2][3] = packh2(S[2 * ks2 + 1][2], S[2 * ks2 + 1][3]);
        }

        #pragma unroll
        for (int ks2 = 0; ks2 < 4; ks2++) {
            #pragma unroll
            for (int nt = 0; nt < 16; nt++) {
                const __half* vb = Vt + (nt * 8 + grp) * 72 + ks2 * 16 + 2 * kq;
                uint32_t b[2];
                b[0] = *(const uint32_t*)vb;
                b[1] = *(const uint32_t*)(vb + 8);
                mma_f16(O[nt], pa[ks2], b);
            }
        }
        __syncthreads();
    }

    // --- epilogue: img rows -> fp16 for Wo GEMM, txt rows -> d_out ---
    const float inv0 = 1.0f / lrow0, inv1 = 1.0f / lrow1;
    const int r = q0 + m0 + grp;
    if (blockIdx.x < 16) {
        #pragma unroll
        for (int nt = 0; nt < 16; nt++) {
            int cc = h * HD + nt * 8 + 2 * kq;
            *reinterpret_cast<__half2*>(&g_ah[(size_t)r * DIM + cc]) =
                __floats2half2_rn(O[nt][0] * inv0, O[nt][1] * inv0);
            *reinterpret_cast<__half2*>(&g_ah[(size_t)(r + 8) * DIM + cc]) =
                __floats2half2_rn(O[nt][2] * inv1, O[nt][3] * inv1);
        }
    } else {
        #pragma unroll
        for (int nt = 0; nt < 16; nt++) {
            int cc = h * HD + nt * 8 + 2 * kq;
            *reinterpret_cast<float2*>(&out[(size_t)r * DIM + cc]) =
                make_float2(O[nt][0] * inv0, O[nt][1] * inv0);
            *reinterpret_cast<float2*>(&out[(size_t)(r + 8) * DIM + cc]) =
                make_float2(O[nt][2] * inv1, O[nt][3] * inv1);
        }
    }
}

// ---------------- launch ----------------
extern "C" void kernel_launch(void* const* d_in, const int* in_sizes, int n_in,
                              void* d_out, int out_size) {
    const float* hid  = (const float*)d_in[0];
    const float* enc  = (const float*)d_in[1];
    const float* rcos = (const float*)d_in[2];
    const float* rsin = (const float*)d_in[3];
    const float* Wq   = (const float*)d_in[4];
    const float* bq   = (const float*)d_in[5];
    const float* Wk   = (const float*)d_in[6];
    const float* bk   = (const float*)d_in[7];
    const float* Wv   = (const float*)d_in[8];
    const float* bv   = (const float*)d_in[9];
    const float* nqw  = (const float*)d_in[10];
    const float* nkw  = (const float*)d_in[11];
    const float* Wo   = (const float*)d_in[12];
    const float* bo   = (const float*)d_in[13];
    float* out = (float*)d_out;

    float *pq, *pk, *pv;
    cudaGetSymbolAddress((void**)&pq, g_q);
    cudaGetSymbolAddress((void**)&pk, g_k);
    cudaGetSymbolAddress((void**)&pv, g_v);
    __half *pxh, *pqh, *pql, *pkh, *pkl, *pah;
    __half *pwqh, *pwkh, *pwvh, *pwoh;
    cudaGetSymbolAddress((void**)&pxh, g_xh);
    cudaGetSymbolAddress((void**)&pqh, g_qh);
    cudaGetSymbolAddress((void**)&pql, g_ql);
    cudaGetSymbolAddress((void**)&pkh, g_kh);
    cudaGetSymbolAddress((void**)&pkl, g_kl);
    cudaGetSymbolAddress((void**)&pah, g_ah);
    cudaGetSymbolAddress((void**)&pwqh, g_wqh);
    cudaGetSymbolAddress((void**)&pwkh, g_wkh);
    cudaGetSymbolAddress((void**)&pwvh, g_wvh);
    cudaGetSymbolAddress((void**)&pwoh, g_woh);

    cudaFuncSetAttribute(gemm_f16, cudaFuncAttributeMaxDynamicSharedMemorySize, GEMM_SMEM);
    cudaFuncSetAttribute(attn_tc, cudaFuncAttributeMaxDynamicSharedMemorySize, ATTN_SMEM);

    concat_xh<<<SEQ * DIM / 1024, 256>>>(hid, enc);

    const int nw4 = DIM * DIM / 1024;
    conv_wh<<<nw4, 256>>>(Wq, pwqh);
    conv_wh<<<nw4, 256>>>(Wk, pwkh);
    conv_wh<<<nw4, 256>>>(Wv, pwvh);
    conv_wh<<<nw4, 256>>>(Wo, pwoh);

    dim3 gqkv(DIM / 128, SEQ / 128);
    gemm_f16<<<gqkv, 256, GEMM_SMEM>>>(pxh, pwqh, bq, pq, SEQ, DIM, DIM);
    gemm_f16<<<gqkv, 256, GEMM_SMEM>>>(pxh, pwkh, bk, pk, SEQ, DIM, DIM);
    gemm_f16<<<gqkv, 256, GEMM_SMEM>>>(pxh, pwvh, bv, pv, SEQ, DIM, DIM);

    dim3 gn(SEQ, HEADS);
    norm_rope_split<<<gn, 128>>>(pq, nqw, rcos, rsin, pqh, pql, QSCALE);
    norm_rope_split<<<gn, 128>>>(pk, nkw, rcos, rsin, pkh, pkl, 1.0f);
    convert_vh<<<SEQ * DIM / 1024, 256>>>();

    dim3 ga(SEQ / 128, HEADS);
    attn_tc<<<ga, 256, ATTN_SMEM>>>(out);

    dim3 gout(DIM / 128, S_IMG / 128);
    gemm_f16<<<gout, 256, GEMM_SMEM>>>(pah, pwoh, bo, out, S_IMG, DIM, DIM);
}